// round 12
// baseline (speedup 1.0000x reference)
#include <cuda_runtime.h>
#include <cuda_bf16.h>
#include <math.h>
#include <stdint.h>

// ---------------- problem constants ----------------
#define HImg   160
#define WImg   160
#define NN     (HImg * WImg)      // 25600
#define C1     128
#define C2     256
#define NHEADS 8
#define DHEAD  32
#define LDS_P  40                 // padded smem row stride in bf16 elems (80B)

// ---------------- device scratch ----------------
__device__ float g_xf[NN * C2];          // node features [N,C2] fp32 (residual)
__device__ float g_h [NN * C2];          // hop features [N,C2]
__device__ float g_id[NN * C2];          // identity path CHW [C2][N]
__device__ float g_y [NN * C2];          // w_out output CHW [C2][N]
__device__ float g_als[NN * NHEADS];
__device__ float g_ald[NN * NHEADS];
__device__ float g_csum[C2];
__device__ float g_sescale[C2];
// pre-split A matrices (bf16 hi/lo)
__device__ __nv_bfloat16 g_ah0[NN * C1]; // xT split  [N][C1]
__device__ __nv_bfloat16 g_al0[NN * C1];
__device__ __nv_bfloat16 g_ah [NN * C2]; // xf split  [N][C2]
__device__ __nv_bfloat16 g_al [NN * C2];
// pre-split weights (bf16 hi/lo): [w_in 32768][w_id 32768][w_gat 131072][w_out 65536]
#define W_TOTAL 262144
#define WIN_OFF   0
#define WGAT_OFF  65536
#define WOUT_OFF  196608
__device__ __nv_bfloat16 g_wh[W_TOTAL];
__device__ __nv_bfloat16 g_wl[W_TOTAL];

// ---------------- helpers ----------------
__device__ __forceinline__ uint32_t smem_u32(const void* p) {
    uint32_t a;
    asm("{ .reg .u64 t; cvta.to.shared.u64 t, %1; cvt.u32.u64 %0, t; }" : "=r"(a) : "l"(p));
    return a;
}
__device__ __forceinline__ void ldsm4(uint32_t* r, uint32_t addr) {
    asm volatile("ldmatrix.sync.aligned.m8n8.x4.shared.b16 {%0, %1, %2, %3}, [%4];"
        : "=r"(r[0]), "=r"(r[1]), "=r"(r[2]), "=r"(r[3]) : "r"(addr));
}
__device__ __forceinline__ void mma_bf16(float* c, const uint32_t* a, const uint32_t* b) {
    asm volatile("mma.sync.aligned.m16n8k16.row.col.f32.bf16.bf16.f32 "
        "{%0, %1, %2, %3}, {%4, %5, %6, %7}, {%8, %9}, {%0, %1, %2, %3};"
        : "+f"(c[0]), "+f"(c[1]), "+f"(c[2]), "+f"(c[3])
        : "r"(a[0]), "r"(a[1]), "r"(a[2]), "r"(a[3]), "r"(b[0]), "r"(b[1]));
}
#define CP_ASYNC16(dst, src) \
    asm volatile("cp.async.cg.shared.global [%0], [%1], 16;" :: "r"(dst), "l"(src) : "memory")
#define CP_COMMIT() asm volatile("cp.async.commit_group;" ::: "memory")
#define CP_WAIT0()  asm volatile("cp.async.wait_group 0;" ::: "memory")

__device__ __forceinline__ void split2(float v0, float v1,
                                       __nv_bfloat162* ph, __nv_bfloat162* pl) {
    __nv_bfloat16 h0 = __float2bfloat16(v0), h1 = __float2bfloat16(v1);
    __nv_bfloat16 l0 = __float2bfloat16(v0 - __bfloat162float(h0));
    __nv_bfloat16 l1 = __float2bfloat16(v1 - __bfloat162float(h1));
    *ph = __halves2bfloat162(h0, h1);
    *pl = __halves2bfloat162(l0, l1);
}

#define FMA8(a, wt, v0, v1) do { \
    (a)[0] = fmaf(wt, v0.x, (a)[0]); (a)[1] = fmaf(wt, v0.y, (a)[1]); \
    (a)[2] = fmaf(wt, v0.z, (a)[2]); (a)[3] = fmaf(wt, v0.w, (a)[3]); \
    (a)[4] = fmaf(wt, v1.x, (a)[4]); (a)[5] = fmaf(wt, v1.y, (a)[5]); \
    (a)[6] = fmaf(wt, v1.z, (a)[6]); (a)[7] = fmaf(wt, v1.w, (a)[7]); } while (0)

// ---------------- transpose + split: x [C1][N] -> split xT [N][C1] ----------------
__global__ void transpose_kernel(const float* __restrict__ x) {
    __shared__ float t[32][33];
    const int n0 = blockIdx.x * 32, c0 = blockIdx.y * 32;
    const int tx = threadIdx.x, ty = threadIdx.y;
#pragma unroll
    for (int k = 0; k < 4; k++)
        t[ty + 8 * k][tx] = x[(size_t)(c0 + ty + 8 * k) * NN + n0 + tx];
    __syncthreads();
#pragma unroll
    for (int k = 0; k < 4; k++) {
        float v = t[tx][ty + 8 * k];
        __nv_bfloat16 h = __float2bfloat16(v);
        size_t o = (size_t)(n0 + ty + 8 * k) * C1 + c0 + tx;
        g_ah0[o] = h;
        g_al0[o] = __float2bfloat16(v - __bfloat162float(h));
    }
}

// ---------------- pre-split weights to bf16 hi/lo (+ zero csum) ----------------
__global__ void wsplit_kernel(const float* __restrict__ w_in, const float* __restrict__ w_id,
                              const float* __restrict__ w_gat, const float* __restrict__ w_out)
{
    int i = blockIdx.x * 256 + threadIdx.x;
    if (blockIdx.x == 0) g_csum[threadIdx.x] = 0.0f;
    float v;
    if      (i < 32768)  v = w_in[i];
    else if (i < 65536)  v = w_id[i - 32768];
    else if (i < 196608) v = w_gat[i - 65536];
    else                 v = w_out[i - 196608];
    __nv_bfloat16 h = __float2bfloat16(v);
    g_wh[i] = h;
    g_wl[i] = __float2bfloat16(v - __bfloat162float(h));
}

// ---------------- bf16-split tensor-core GEMM, 128x64 tiles ----------------
// C[M,...] = A[M,K] @ B[.,K]^T, 2-term bf16 split (hi*hi + hi*lo + lo*hi).
// 128x64 block tile (finer N) to reduce wave-quantization tail:
// hop/wout GEMMs go 400 CTAs/2 waves -> 800 CTAs/3 half-duration waves (1.5T vs 2T).
// Warps: 4 (m) x 2 (n); warp tile 32 rows x 32 cols (32-col span == one head).
// EPI 0: grid.y=8: cols 0-255 -> g_xf + split; 256-511 -> g_id CHW
// EPI 1: grid.y=4: -> g_h row-major + FUSED attention logits
// EPI 2: grid.y=4: -> g_y CHW + FUSED SE column sums
#define ASTG  10240               // A sub-array bytes per stage (128 rows * 80B)
#define BSTG  5120                // B sub-array bytes per stage (64 rows * 80B)
#define STAGE 30720               // Ah + Al + Bh + Bl
template<int KTOT, int EPI>
__global__ __launch_bounds__(256, 2)
void gemm_mma(const __nv_bfloat16* __restrict__ Bh_base,
              const __nv_bfloat16* __restrict__ Bl_base,
              const float* __restrict__ asrc, const float* __restrict__ adst)
{
    extern __shared__ char smem[];
    __shared__ float s_as[C2], s_ad[C2];
    const uint32_t uS = smem_u32(smem);

    const int tid = threadIdx.x;
    const int m0  = blockIdx.x * 128;
    const int nb  = blockIdx.y;
    const __nv_bfloat16* Ah = (EPI == 0) ? g_ah0 : g_ah;
    const __nv_bfloat16* Al = (EPI == 0) ? g_al0 : g_al;
    const __nv_bfloat16* Bh = Bh_base + (size_t)nb * 64 * KTOT;
    const __nv_bfloat16* Bl = Bl_base + (size_t)nb * 64 * KTOT;

    if (EPI == 1) { s_as[tid] = asrc[tid]; s_ad[tid] = adst[tid]; }

    auto cp_chunk = [&](int c, int st) {
        const int k0 = c * 32;
        const uint32_t base = uS + st * STAGE;
        // A: 128 rows x 4 segs = 512 segs per array -> 2 iterations
#pragma unroll
        for (int it = 0; it < 2; it++) {
            const int idx = tid + it * 256;
            const int row = idx >> 2, seg = idx & 3;
            const uint32_t dro = row * (LDS_P * 2) + seg * 16;
            const size_t ao = (size_t)(m0 + row) * KTOT + k0 + seg * 8;
            CP_ASYNC16(base + dro,        Ah + ao);
            CP_ASYNC16(base + ASTG + dro, Al + ao);
        }
        // B: 64 rows x 4 segs = 256 segs per array -> 1 iteration
        {
            const int row = tid >> 2, seg = tid & 3;
            const uint32_t dro = row * (LDS_P * 2) + seg * 16;
            const size_t bo = (size_t)row * KTOT + k0 + seg * 8;
            CP_ASYNC16(base + 2 * ASTG + dro,        Bh + bo);
            CP_ASYNC16(base + 2 * ASTG + BSTG + dro, Bl + bo);
        }
        CP_COMMIT();
    };

    // warp tiling: 8 warps = 4 (m) x 2 (n); warp tile 32 rows x 32 cols
    const int w = tid >> 5, lane = tid & 31;
    const int wm = (w & 3) * 32;
    const int wn = (w >> 2) * 32;

    const int a_row = (lane < 16) ? lane : (lane - 16);
    const int a_kc  = (lane < 16) ? 0 : 8;
    const int b_row = (lane & 7) + ((lane & 16) >> 1);
    const int b_kc  = (lane & 8) ? 8 : 0;

    float acc[2][4][4];
#pragma unroll
    for (int mi = 0; mi < 2; mi++)
#pragma unroll
        for (int ni = 0; ni < 4; ni++)
#pragma unroll
            for (int r = 0; r < 4; r++) acc[mi][ni][r] = 0.0f;

    constexpr int NC = KTOT / 32;
    cp_chunk(0, 0);
    for (int c = 0; c < NC; c++) {
        const int st = c & 1;
        CP_WAIT0();
        __syncthreads();
        if (c + 1 < NC) cp_chunk(c + 1, st ^ 1);   // overlaps compute below
        const uint32_t sb = uS + st * STAGE;
#pragma unroll
        for (int ks = 0; ks < 2; ks++) {
            const int k0 = ks * 16;
            uint32_t bh[4][2], bl[4][2];
#pragma unroll
            for (int np = 0; np < 2; np++) {
                const uint32_t off = (uint32_t)(((wn + np * 16 + b_row) * LDS_P + k0 + b_kc) * 2);
                uint32_t r4[4];
                ldsm4(r4, sb + 2 * ASTG + off);
                bh[2 * np][0] = r4[0]; bh[2 * np][1] = r4[1];
                bh[2 * np + 1][0] = r4[2]; bh[2 * np + 1][1] = r4[3];
                ldsm4(r4, sb + 2 * ASTG + BSTG + off);
                bl[2 * np][0] = r4[0]; bl[2 * np][1] = r4[1];
                bl[2 * np + 1][0] = r4[2]; bl[2 * np + 1][1] = r4[3];
            }
#pragma unroll
            for (int mi = 0; mi < 2; mi++) {
                const uint32_t off = (uint32_t)(((wm + mi * 16 + a_row) * LDS_P + k0 + a_kc) * 2);
                uint32_t ah[4], al[4];
                ldsm4(ah, sb + off);
                ldsm4(al, sb + ASTG + off);
                // term-swept: consecutive MMAs target different accumulators
#pragma unroll
                for (int ni = 0; ni < 4; ni++) mma_bf16(acc[mi][ni], ah, bh[ni]);
#pragma unroll
                for (int ni = 0; ni < 4; ni++) mma_bf16(acc[mi][ni], ah, bl[ni]);
#pragma unroll
                for (int ni = 0; ni < 4; ni++) mma_bf16(acc[mi][ni], al, bh[ni]);
            }
        }
    }

    // ---- epilogue ----
    const int qr = lane >> 2;
    const int qc = (lane & 3) * 2;
#pragma unroll
    for (int mi = 0; mi < 2; mi++) {
#pragma unroll
        for (int ni = 0; ni < 4; ni++) {
            const int m  = m0 + wm + mi * 16 + qr;
            const int gn = nb * 64 + wn + ni * 8 + qc;
            const float* a4 = acc[mi][ni];
            if (EPI == 0) {
                if (gn < 256) {
                    *(float2*)&g_xf[(size_t)m * C2 + gn]       = make_float2(a4[0], a4[1]);
                    *(float2*)&g_xf[(size_t)(m + 8) * C2 + gn] = make_float2(a4[2], a4[3]);
                    __nv_bfloat162 ph, pl;
                    split2(a4[0], a4[1], &ph, &pl);
                    *(__nv_bfloat162*)&g_ah[(size_t)m * C2 + gn] = ph;
                    *(__nv_bfloat162*)&g_al[(size_t)m * C2 + gn] = pl;
                    split2(a4[2], a4[3], &ph, &pl);
                    *(__nv_bfloat162*)&g_ah[(size_t)(m + 8) * C2 + gn] = ph;
                    *(__nv_bfloat162*)&g_al[(size_t)(m + 8) * C2 + gn] = pl;
                } else {
                    const int ch = gn - 256;
                    g_id[(size_t)ch * NN + m]           = a4[0];
                    g_id[(size_t)(ch + 1) * NN + m]     = a4[1];
                    g_id[(size_t)ch * NN + m + 8]       = a4[2];
                    g_id[(size_t)(ch + 1) * NN + m + 8] = a4[3];
                }
            } else if (EPI == 1) {
                *(float2*)&g_h[(size_t)m * C2 + gn]       = make_float2(a4[0], a4[1]);
                *(float2*)&g_h[(size_t)(m + 8) * C2 + gn] = make_float2(a4[2], a4[3]);
            } else {
                g_y[(size_t)gn * NN + m]           = a4[0];
                g_y[(size_t)(gn + 1) * NN + m]     = a4[1];
                g_y[(size_t)gn * NN + m + 8]       = a4[2];
                g_y[(size_t)(gn + 1) * NN + m + 8] = a4[3];
            }
        }
    }

    if (EPI == 1) {
        // fused attention logits: warp's 32 columns == one head
        const int hd = (nb * 64 + wn) >> 5;
#pragma unroll
        for (int mi = 0; mi < 2; mi++) {
            float s0 = 0.0f, d0 = 0.0f, s1 = 0.0f, d1 = 0.0f;
#pragma unroll
            for (int ni = 0; ni < 4; ni++) {
                const int gc = nb * 64 + wn + ni * 8 + qc;
                const float a0 = s_as[gc], a1 = s_as[gc + 1];
                const float b0 = s_ad[gc], b1 = s_ad[gc + 1];
                const float* a4 = acc[mi][ni];
                s0 = fmaf(a4[0], a0, fmaf(a4[1], a1, s0));
                d0 = fmaf(a4[0], b0, fmaf(a4[1], b1, d0));
                s1 = fmaf(a4[2], a0, fmaf(a4[3], a1, s1));
                d1 = fmaf(a4[2], b0, fmaf(a4[3], b1, d1));
            }
            s0 += __shfl_xor_sync(~0u, s0, 1); s0 += __shfl_xor_sync(~0u, s0, 2);
            d0 += __shfl_xor_sync(~0u, d0, 1); d0 += __shfl_xor_sync(~0u, d0, 2);
            s1 += __shfl_xor_sync(~0u, s1, 1); s1 += __shfl_xor_sync(~0u, s1, 2);
            d1 += __shfl_xor_sync(~0u, d1, 1); d1 += __shfl_xor_sync(~0u, d1, 2);
            if ((lane & 3) == 0) {
                const int m = m0 + wm + mi * 16 + qr;
                g_als[m * NHEADS + hd] = s0;
                g_ald[m * NHEADS + hd] = d0;
                g_als[(m + 8) * NHEADS + hd] = s1;
                g_ald[(m + 8) * NHEADS + hd] = d1;
            }
        }
    }

    if (EPI == 2) {
        // fused SE column sums
        float cs[4][2];
#pragma unroll
        for (int ni = 0; ni < 4; ni++) {
            cs[ni][0] = 0.0f; cs[ni][1] = 0.0f;
#pragma unroll
            for (int mi = 0; mi < 2; mi++) {
                cs[ni][0] += acc[mi][ni][0] + acc[mi][ni][2];
                cs[ni][1] += acc[mi][ni][1] + acc[mi][ni][3];
            }
        }
#pragma unroll
        for (int ni = 0; ni < 4; ni++)
#pragma unroll
            for (int v = 0; v < 2; v++) {
                float t = cs[ni][v];
                t += __shfl_xor_sync(~0u, t, 4);
                t += __shfl_xor_sync(~0u, t, 8);
                t += __shfl_xor_sync(~0u, t, 16);
                cs[ni][v] = t;
            }
        if (lane < 4) {
#pragma unroll
            for (int ni = 0; ni < 4; ni++)
#pragma unroll
                for (int v = 0; v < 2; v++)
                    atomicAdd(&g_csum[nb * 64 + wn + ni * 8 + lane * 2 + v], cs[ni][v]);
        }
    }
}

// ---------------- GAT stencil hop: dedup softmax + source-union gather ----------------
__global__ __launch_bounds__(256)
void gat_stencil_kernel(const float* __restrict__ h,
                        const float* __restrict__ bias,
                        const float* __restrict__ gamma,
                        const float* __restrict__ beta,
                        const float* __restrict__ mean,
                        const float* __restrict__ var)
{
    __shared__ float s_bias[C2], s_scale[C2], s_shift[C2];
    __shared__ float sw[32][NHEADS][12];
    const int tid = threadIdx.x;
    {
        float sc = gamma[tid] * rsqrtf(var[tid] + 1e-5f);
        s_bias[tid]  = bias[tid];
        s_scale[tid] = sc;
        s_shift[tid] = beta[tid] - mean[tid] * sc;
    }

    const int nb0 = blockIdx.x * 32;

    // ---- phase 1 ----
    {
        const int di[11] = {-1, -1, -1,  0, 0,  1, 1, 1,  2, 0, 0};
        const int dj[11] = {-1,  0,  1, -1, 1, -1, 0, 1,  0, 2, 0};
        const int nl = tid >> 3, head = tid & 7;
        const int n = nb0 + nl;
        const int i = n / WImg, j = n % WImg;
        const float ald_v = g_ald[n * NHEADS + head];
        float ev[11];
        float mx = -1e30f;
#pragma unroll
        for (int k = 0; k < 11; k++) {
            int si = i - di[k], sj = j - dj[k];
            if ((unsigned)si < HImg && (unsigned)sj < WImg) {
                float e = g_als[(si * WImg + sj) * NHEADS + head] + ald_v;
                e = (e > 0.0f) ? e : 0.2f * e;
                ev[k] = e;
                mx = fmaxf(mx, e);
            } else ev[k] = -1e30f;
        }
        float sum = 0.0f;
#pragma unroll
        for (int k = 0; k < 11; k++) {
            float a = (ev[k] > -1e29f) ? expf(ev[k] - mx) : 0.0f;
            ev[k] = a;
            sum += a;
        }
        const float inv = 1.0f / (sum + 1e-16f);
#pragma unroll
        for (int k = 0; k < 11; k++) sw[nl][head][k] = ev[k] * inv;
    }
    __syncthreads();

    // ---- phase 2: warp per 4 nodes, source-union streaming ----
    const int w = tid >> 5, lane = tid & 31;
    const int head = lane >> 2;
    const int cb = lane * 8;
    const int j0l = w * 4;
    const int n0w = nb0 + j0l;
    const int i = n0w / WImg, j0 = n0w % WImg;

    float acc[4][8];
#pragma unroll
    for (int t = 0; t < 4; t++)
#pragma unroll
        for (int q = 0; q < 8; q++) acc[t][q] = 0.0f;

    if (i + 1 < HImg) {
        const float* rb = h + (size_t)(i + 1) * WImg * C2 + cb;
#pragma unroll
        for (int uu = -1; uu <= 4; uu++) {
            const int scn = j0 + uu;
            if ((unsigned)scn < WImg) {
                const float4* hp = (const float4*)(rb + (size_t)scn * C2);
                float4 v0 = hp[0], v1 = hp[1];
#pragma unroll
                for (int dj = -1; dj <= 1; dj++) {
                    const int t = uu + dj;
                    if (t >= 0 && t < 4) {
                        const float wt = sw[j0l + t][head][dj + 1];
                        FMA8(acc[t], wt, v0, v1);
                    }
                }
            }
        }
    }
    {
        const float* rb = h + (size_t)i * WImg * C2 + cb;
        const int djs[4] = {-1, 0, 1, 2};
        const int tps[4] = {3, 10, 4, 9};
#pragma unroll
        for (int uu = -2; uu <= 4; uu++) {
            const int scn = j0 + uu;
            if ((unsigned)scn < WImg) {
                const float4* hp = (const float4*)(rb + (size_t)scn * C2);
                float4 v0 = hp[0], v1 = hp[1];
#pragma unroll
                for (int q = 0; q < 4; q++) {
                    const int t = uu + djs[q];
                    if (t >= 0 && t < 4) {
                        const float wt = sw[j0l + t][head][tps[q]];
                        FMA8(acc[t], wt, v0, v1);
                    }
                }
            }
        }
    }
    if (i - 1 >= 0) {
        const float* rb = h + (size_t)(i - 1) * WImg * C2 + cb;
#pragma unroll
        for (int uu = -1; uu <= 4; uu++) {
            const int scn = j0 + uu;
            if ((unsigned)scn < WImg) {
                const float4* hp = (const float4*)(rb + (size_t)scn * C2);
                float4 v0 = hp[0], v1 = hp[1];
#pragma unroll
                for (int dj = -1; dj <= 1; dj++) {
                    const int t = uu + dj;
                    if (t >= 0 && t < 4) {
                        const float wt = sw[j0l + t][head][dj + 6];
                        FMA8(acc[t], wt, v0, v1);
                    }
                }
            }
        }
    }
    if (i - 2 >= 0) {
        const float* rb = h + (size_t)(i - 2) * WImg * C2 + cb;
#pragma unroll
        for (int uu = 0; uu <= 3; uu++) {
            const int scn = j0 + uu;
            const float4* hp = (const float4*)(rb + (size_t)scn * C2);
            float4 v0 = hp[0], v1 = hp[1];
            const float wt = sw[j0l + uu][head][8];
            FMA8(acc[uu], wt, v0, v1);
        }
    }

#pragma unroll
    for (int t = 0; t < 4; t++) {
        const int n = n0w + t;
        float4* xp = (float4*)&g_xf[(size_t)n * C2 + cb];
        float4 x0 = xp[0], x1 = xp[1];
        float o[8] = {x0.x, x0.y, x0.z, x0.w, x1.x, x1.y, x1.z, x1.w};
#pragma unroll
        for (int q = 0; q < 8; q++) {
            int c = cb + q;
            float g = acc[t][q] + s_bias[c];
            g = fmaf(g, s_scale[c], s_shift[c]);
            g = fmaxf(g, 0.0f);
            o[q] += g;
        }
        xp[0] = make_float4(o[0], o[1], o[2], o[3]);
        xp[1] = make_float4(o[4], o[5], o[6], o[7]);

        __nv_bfloat162 ph[4], pl[4];
#pragma unroll
        for (int q = 0; q < 4; q++) split2(o[2 * q], o[2 * q + 1], &ph[q], &pl[q]);
        *(uint4*)&g_ah[(size_t)n * C2 + cb] = *(uint4*)ph;
        *(uint4*)&g_al[(size_t)n * C2 + cb] = *(uint4*)pl;
    }
}

// ---------------- SE block ----------------
__global__ void se_kernel(const float* __restrict__ w1, const float* __restrict__ b1,
                          const float* __restrict__ w2, const float* __restrict__ b2)
{
    __shared__ float mean_s[C2];
    __shared__ float t1[64];
    const int tx = threadIdx.x;
    mean_s[tx] = g_csum[tx] * (1.0f / (float)NN);
    __syncthreads();
    if (tx < 64) {
        float a = b1[tx];
        for (int c = 0; c < C2; c++) a = fmaf(mean_s[c], w1[tx * C2 + c], a);
        t1[tx] = fmaxf(a, 0.0f);
    }
    __syncthreads();
    float a = b2[tx];
#pragma unroll
    for (int jq = 0; jq < 64; jq++) a = fmaf(t1[jq], w2[tx * 64 + jq], a);
    g_sescale[tx] = 1.0f / (1.0f + expf(-a));
}

// ---------------- final fuse: out = y * se + identity (CHW) ----------------
__global__ void final_kernel(float* __restrict__ out) {
    int idx = blockIdx.x * blockDim.x + threadIdx.x;
    int e = idx * 4;
    int c = e / NN;
    float s = g_sescale[c];
    float4 y  = *(const float4*)&g_y[e];
    float4 id = *(const float4*)&g_id[e];
    float4 o;
    o.x = fmaf(y.x, s, id.x); o.y = fmaf(y.y, s, id.y);
    o.z = fmaf(y.z, s, id.z); o.w = fmaf(y.w, s, id.w);
    *(float4*)&out[e] = o;
}

// ---------------- launch ----------------
extern "C" void kernel_launch(void* const* d_in, const int* in_sizes, int n_in,
                              void* d_out, int out_size)
{
    const float* x        = (const float*)d_in[0];
    const float* w_id     = (const float*)d_in[1];
    const float* w_in     = (const float*)d_in[2];
    const float* w_gat    = (const float*)d_in[3];
    const float* a_src    = (const float*)d_in[4];
    const float* a_dst    = (const float*)d_in[5];
    const float* gat_bias = (const float*)d_in[6];
    const float* bn_gamma = (const float*)d_in[7];
    const float* bn_beta  = (const float*)d_in[8];
    const float* bn_mean  = (const float*)d_in[9];
    const float* bn_var   = (const float*)d_in[10];
    const float* w_out    = (const float*)d_in[11];
    const float* se_w1    = (const float*)d_in[12];
    const float* se_b1    = (const float*)d_in[13];
    const float* se_w2    = (const float*)d_in[14];
    const float* se_b2    = (const float*)d_in[15];
    float* out = (float*)d_out;

    float* hb;
    __nv_bfloat16 *wh, *wl;
    cudaGetSymbolAddress((void**)&hb, g_h);
    cudaGetSymbolAddress((void**)&wh, g_wh);
    cudaGetSymbolAddress((void**)&wl, g_wl);

    constexpr int SMEM_GEMM = 2 * STAGE;   // 61440 bytes
    cudaFuncSetAttribute(gemm_mma<C1, 0>, cudaFuncAttributeMaxDynamicSharedMemorySize, SMEM_GEMM);
    cudaFuncSetAttribute(gemm_mma<C2, 1>, cudaFuncAttributeMaxDynamicSharedMemorySize, SMEM_GEMM);
    cudaFuncSetAttribute(gemm_mma<C2, 2>, cudaFuncAttributeMaxDynamicSharedMemorySize, SMEM_GEMM);

    // 1) transpose+split x; split weights (+ zero csum)
    transpose_kernel<<<dim3(NN / 32, C1 / 32), dim3(32, 8)>>>(x);
    wsplit_kernel<<<W_TOTAL / 256, 256>>>(w_in, w_id, w_gat, w_out);

    // 2) fused: xf = xT @ w_in^T (row-major + split) + id = xT @ w_id^T (CHW)
    gemm_mma<C1, 0><<<dim3(NN / 128, 8), 256, SMEM_GEMM>>>(wh + WIN_OFF, wl + WIN_OFF,
                                                           nullptr, nullptr);

    // 3) GAT hops (logits fused into GEMM epilogue)
    for (int l = 0; l < 2; l++) {
        gemm_mma<C2, 1><<<dim3(NN / 128, 4), 256, SMEM_GEMM>>>(
            wh + WGAT_OFF + (size_t)l * C2 * C2, wl + WGAT_OFF + (size_t)l * C2 * C2,
            a_src + l * NHEADS * DHEAD, a_dst + l * NHEADS * DHEAD);
        gat_stencil_kernel<<<NN / 32, 256>>>(
            hb, gat_bias + l * C2, bn_gamma + l * C2, bn_beta + l * C2,
            bn_mean + l * C2, bn_var + l * C2);
    }

    // 4) y = xf @ w_out^T (CHW) + fused SE column sums
    gemm_mma<C2, 2><<<dim3(NN / 128, 4), 256, SMEM_GEMM>>>(wh + WOUT_OFF, wl + WOUT_OFF,
                                                           nullptr, nullptr);

    // 5) SE + final fuse
    se_kernel<<<1, C2>>>(se_w1, se_b1, se_w2, se_b2);
    final_kernel<<<(NN * C2 / 4) / 256, 256>>>(out);
}

// round 14
// speedup vs baseline: 1.0980x; 1.0980x over previous
#include <cuda_runtime.h>
#include <cuda_bf16.h>
#include <math.h>
#include <stdint.h>

// ---------------- problem constants ----------------
#define HImg   160
#define WImg   160
#define NN     (HImg * WImg)      // 25600
#define C1     128
#define C2     256
#define NHEADS 8
#define DHEAD  32
#define LDS_P  40                 // padded smem row stride in bf16 elems (80B)

// ---------------- device scratch ----------------
__device__ float g_xf[NN * C2];          // node features [N,C2] fp32 (residual)
__device__ float g_h [NN * C2];          // hop features [N,C2]
__device__ float g_id[NN * C2];          // identity path CHW [C2][N]
__device__ float g_y [NN * C2];          // w_out output CHW [C2][N]
__device__ float g_als[NN * NHEADS];
__device__ float g_ald[NN * NHEADS];
__device__ float g_csum[C2];
// pre-split A matrices (bf16 hi/lo)
__device__ __nv_bfloat16 g_ah0[NN * C1]; // xT split  [N][C1]
__device__ __nv_bfloat16 g_al0[NN * C1];
__device__ __nv_bfloat16 g_ah [NN * C2]; // xf split  [N][C2]
__device__ __nv_bfloat16 g_al [NN * C2];
// pre-split weights (bf16 hi/lo): [w_in 32768][w_id 32768][w_gat 131072][w_out 65536]
#define W_TOTAL 262144
#define WIN_OFF   0
#define WGAT_OFF  65536
#define WOUT_OFF  196608
__device__ __nv_bfloat16 g_wh[W_TOTAL];
__device__ __nv_bfloat16 g_wl[W_TOTAL];

// ---------------- helpers ----------------
__device__ __forceinline__ uint32_t smem_u32(const void* p) {
    uint32_t a;
    asm("{ .reg .u64 t; cvta.to.shared.u64 t, %1; cvt.u32.u64 %0, t; }" : "=r"(a) : "l"(p));
    return a;
}
__device__ __forceinline__ void ldsm4(uint32_t* r, uint32_t addr) {
    asm volatile("ldmatrix.sync.aligned.m8n8.x4.shared.b16 {%0, %1, %2, %3}, [%4];"
        : "=r"(r[0]), "=r"(r[1]), "=r"(r[2]), "=r"(r[3]) : "r"(addr));
}
__device__ __forceinline__ void mma_bf16(float* c, const uint32_t* a, const uint32_t* b) {
    asm volatile("mma.sync.aligned.m16n8k16.row.col.f32.bf16.bf16.f32 "
        "{%0, %1, %2, %3}, {%4, %5, %6, %7}, {%8, %9}, {%0, %1, %2, %3};"
        : "+f"(c[0]), "+f"(c[1]), "+f"(c[2]), "+f"(c[3])
        : "r"(a[0]), "r"(a[1]), "r"(a[2]), "r"(a[3]), "r"(b[0]), "r"(b[1]));
}
#define CP_ASYNC16(dst, src) \
    asm volatile("cp.async.cg.shared.global [%0], [%1], 16;" :: "r"(dst), "l"(src) : "memory")
#define CP_COMMIT() asm volatile("cp.async.commit_group;" ::: "memory")
#define CP_WAIT0()  asm volatile("cp.async.wait_group 0;" ::: "memory")

__device__ __forceinline__ void split2(float v0, float v1,
                                       __nv_bfloat162* ph, __nv_bfloat162* pl) {
    __nv_bfloat16 h0 = __float2bfloat16(v0), h1 = __float2bfloat16(v1);
    __nv_bfloat16 l0 = __float2bfloat16(v0 - __bfloat162float(h0));
    __nv_bfloat16 l1 = __float2bfloat16(v1 - __bfloat162float(h1));
    *ph = __halves2bfloat162(h0, h1);
    *pl = __halves2bfloat162(l0, l1);
}

#define FMA8(a, wt, v0, v1) do { \
    (a)[0] = fmaf(wt, v0.x, (a)[0]); (a)[1] = fmaf(wt, v0.y, (a)[1]); \
    (a)[2] = fmaf(wt, v0.z, (a)[2]); (a)[3] = fmaf(wt, v0.w, (a)[3]); \
    (a)[4] = fmaf(wt, v1.x, (a)[4]); (a)[5] = fmaf(wt, v1.y, (a)[5]); \
    (a)[6] = fmaf(wt, v1.z, (a)[6]); (a)[7] = fmaf(wt, v1.w, (a)[7]); } while (0)

// ---------------- transpose + split: x [C1][N] -> split xT [N][C1] ----------------
__global__ void transpose_kernel(const float* __restrict__ x) {
    __shared__ float t[32][33];
    const int n0 = blockIdx.x * 32, c0 = blockIdx.y * 32;
    const int tx = threadIdx.x, ty = threadIdx.y;
#pragma unroll
    for (int k = 0; k < 4; k++)
        t[ty + 8 * k][tx] = x[(size_t)(c0 + ty + 8 * k) * NN + n0 + tx];
    __syncthreads();
#pragma unroll
    for (int k = 0; k < 4; k++) {
        float v = t[tx][ty + 8 * k];
        __nv_bfloat16 h = __float2bfloat16(v);
        size_t o = (size_t)(n0 + ty + 8 * k) * C1 + c0 + tx;
        g_ah0[o] = h;
        g_al0[o] = __float2bfloat16(v - __bfloat162float(h));
    }
}

// ---------------- pre-split weights to bf16 hi/lo (+ zero csum) ----------------
__global__ void wsplit_kernel(const float* __restrict__ w_in, const float* __restrict__ w_id,
                              const float* __restrict__ w_gat, const float* __restrict__ w_out)
{
    int i = blockIdx.x * 256 + threadIdx.x;
    if (blockIdx.x == 0) g_csum[threadIdx.x] = 0.0f;
    float v;
    if      (i < 32768)  v = w_in[i];
    else if (i < 65536)  v = w_id[i - 32768];
    else if (i < 196608) v = w_gat[i - 65536];
    else                 v = w_out[i - 196608];
    __nv_bfloat16 h = __float2bfloat16(v);
    g_wh[i] = h;
    g_wl[i] = __float2bfloat16(v - __bfloat162float(h));
}

// ---------------- bf16-split tensor-core GEMM, all-cp.async mainloop ----------------
// Term-swept inner loop; fused epilogues. 128x128 block tile (verified best).
#define STG 10240                 // bytes per sub-array per stage
template<int KTOT, int EPI>
__global__ __launch_bounds__(256, 2)
void gemm_mma(const __nv_bfloat16* __restrict__ Bh_base,
              const __nv_bfloat16* __restrict__ Bl_base,
              const float* __restrict__ asrc, const float* __restrict__ adst)
{
    extern __shared__ char smem[];
    __shared__ float s_as[C2], s_ad[C2];
    const uint32_t uS = smem_u32(smem);

    const int tid = threadIdx.x;
    const int m0  = blockIdx.x * 128;
    const int nb  = blockIdx.y;
    const __nv_bfloat16* Ah = (EPI == 0) ? g_ah0 : g_ah;
    const __nv_bfloat16* Al = (EPI == 0) ? g_al0 : g_al;
    const __nv_bfloat16* Bh = Bh_base + (size_t)nb * 128 * KTOT;
    const __nv_bfloat16* Bl = Bl_base + (size_t)nb * 128 * KTOT;

    if (EPI == 1) { s_as[tid] = asrc[tid]; s_ad[tid] = adst[tid]; }

    auto cp_chunk = [&](int c, int st) {
        const int k0 = c * 32;
        const uint32_t base = uS + st * 4 * STG;
#pragma unroll
        for (int it = 0; it < 2; it++) {
            const int idx = tid + it * 256;        // 0..511
            const int row = idx >> 2, seg = idx & 3;
            const uint32_t dro = row * (LDS_P * 2) + seg * 16;
            const size_t ao = (size_t)(m0 + row) * KTOT + k0 + seg * 8;
            const size_t bo = (size_t)row * KTOT + k0 + seg * 8;
            CP_ASYNC16(base + dro,           Ah + ao);
            CP_ASYNC16(base + STG + dro,     Al + ao);
            CP_ASYNC16(base + 2 * STG + dro, Bh + bo);
            CP_ASYNC16(base + 3 * STG + dro, Bl + bo);
        }
        CP_COMMIT();
    };

    // warp tiling: 8 warps = 2 (m) x 4 (n); warp tile 64x32
    const int w = tid >> 5, lane = tid & 31;
    const int wm = (w >> 2) * 64;
    const int wn = (w & 3) * 32;

    const int a_row = (lane < 16) ? lane : (lane - 16);
    const int a_kc  = (lane < 16) ? 0 : 8;
    const int b_row = (lane & 7) + ((lane & 16) >> 1);
    const int b_kc  = (lane & 8) ? 8 : 0;

    float acc[4][4][4];
#pragma unroll
    for (int mi = 0; mi < 4; mi++)
#pragma unroll
        for (int ni = 0; ni < 4; ni++)
#pragma unroll
            for (int r = 0; r < 4; r++) acc[mi][ni][r] = 0.0f;

    constexpr int NC = KTOT / 32;
    cp_chunk(0, 0);
    for (int c = 0; c < NC; c++) {
        const int st = c & 1;
        CP_WAIT0();
        __syncthreads();
        if (c + 1 < NC) cp_chunk(c + 1, st ^ 1);   // overlaps compute below
        const uint32_t sb = uS + st * 4 * STG;
#pragma unroll
        for (int ks = 0; ks < 2; ks++) {
            const int k0 = ks * 16;
            uint32_t bh[4][2], bl[4][2];
#pragma unroll
            for (int np = 0; np < 2; np++) {
                const uint32_t off = (uint32_t)(((wn + np * 16 + b_row) * LDS_P + k0 + b_kc) * 2);
                uint32_t r4[4];
                ldsm4(r4, sb + 2 * STG + off);
                bh[2 * np][0] = r4[0]; bh[2 * np][1] = r4[1];
                bh[2 * np + 1][0] = r4[2]; bh[2 * np + 1][1] = r4[3];
                ldsm4(r4, sb + 3 * STG + off);
                bl[2 * np][0] = r4[0]; bl[2 * np][1] = r4[1];
                bl[2 * np + 1][0] = r4[2]; bl[2 * np + 1][1] = r4[3];
            }
#pragma unroll
            for (int mi = 0; mi < 4; mi++) {
                const uint32_t off = (uint32_t)(((wm + mi * 16 + a_row) * LDS_P + k0 + a_kc) * 2);
                uint32_t ah[4], al[4];
                ldsm4(ah, sb + off);
                ldsm4(al, sb + STG + off);
                // term-swept: consecutive MMAs target different accumulators
#pragma unroll
                for (int ni = 0; ni < 4; ni++) mma_bf16(acc[mi][ni], ah, bh[ni]);
#pragma unroll
                for (int ni = 0; ni < 4; ni++) mma_bf16(acc[mi][ni], ah, bl[ni]);
#pragma unroll
                for (int ni = 0; ni < 4; ni++) mma_bf16(acc[mi][ni], al, bh[ni]);
            }
        }
    }

    // ---- epilogue ----
    const int qr = lane >> 2;
    const int qc = (lane & 3) * 2;
#pragma unroll
    for (int mi = 0; mi < 4; mi++) {
#pragma unroll
        for (int ni = 0; ni < 4; ni++) {
            const int m  = m0 + wm + mi * 16 + qr;
            const int gn = nb * 128 + wn + ni * 8 + qc;
            const float* a4 = acc[mi][ni];
            if (EPI == 0) {
                if (gn < 256) {
                    *(float2*)&g_xf[(size_t)m * C2 + gn]       = make_float2(a4[0], a4[1]);
                    *(float2*)&g_xf[(size_t)(m + 8) * C2 + gn] = make_float2(a4[2], a4[3]);
                    __nv_bfloat162 ph, pl;
                    split2(a4[0], a4[1], &ph, &pl);
                    *(__nv_bfloat162*)&g_ah[(size_t)m * C2 + gn] = ph;
                    *(__nv_bfloat162*)&g_al[(size_t)m * C2 + gn] = pl;
                    split2(a4[2], a4[3], &ph, &pl);
                    *(__nv_bfloat162*)&g_ah[(size_t)(m + 8) * C2 + gn] = ph;
                    *(__nv_bfloat162*)&g_al[(size_t)(m + 8) * C2 + gn] = pl;
                } else {
                    const int ch = gn - 256;
                    g_id[(size_t)ch * NN + m]           = a4[0];
                    g_id[(size_t)(ch + 1) * NN + m]     = a4[1];
                    g_id[(size_t)ch * NN + m + 8]       = a4[2];
                    g_id[(size_t)(ch + 1) * NN + m + 8] = a4[3];
                }
            } else if (EPI == 1) {
                *(float2*)&g_h[(size_t)m * C2 + gn]       = make_float2(a4[0], a4[1]);
                *(float2*)&g_h[(size_t)(m + 8) * C2 + gn] = make_float2(a4[2], a4[3]);
            } else {
                g_y[(size_t)gn * NN + m]           = a4[0];
                g_y[(size_t)(gn + 1) * NN + m]     = a4[1];
                g_y[(size_t)gn * NN + m + 8]       = a4[2];
                g_y[(size_t)(gn + 1) * NN + m + 8] = a4[3];
            }
        }
    }

    if (EPI == 1) {
        // fused attention logits: warp's 32 columns == one head
        const int hd = (nb * 128 + wn) >> 5;
#pragma unroll
        for (int mi = 0; mi < 4; mi++) {
            float s0 = 0.0f, d0 = 0.0f, s1 = 0.0f, d1 = 0.0f;
#pragma unroll
            for (int ni = 0; ni < 4; ni++) {
                const int gc = nb * 128 + wn + ni * 8 + qc;
                const float a0 = s_as[gc], a1 = s_as[gc + 1];
                const float b0 = s_ad[gc], b1 = s_ad[gc + 1];
                const float* a4 = acc[mi][ni];
                s0 = fmaf(a4[0], a0, fmaf(a4[1], a1, s0));
                d0 = fmaf(a4[0], b0, fmaf(a4[1], b1, d0));
                s1 = fmaf(a4[2], a0, fmaf(a4[3], a1, s1));
                d1 = fmaf(a4[2], b0, fmaf(a4[3], b1, d1));
            }
            s0 += __shfl_xor_sync(~0u, s0, 1); s0 += __shfl_xor_sync(~0u, s0, 2);
            d0 += __shfl_xor_sync(~0u, d0, 1); d0 += __shfl_xor_sync(~0u, d0, 2);
            s1 += __shfl_xor_sync(~0u, s1, 1); s1 += __shfl_xor_sync(~0u, s1, 2);
            d1 += __shfl_xor_sync(~0u, d1, 1); d1 += __shfl_xor_sync(~0u, d1, 2);
            if ((lane & 3) == 0) {
                const int m = m0 + wm + mi * 16 + qr;
                g_als[m * NHEADS + hd] = s0;
                g_ald[m * NHEADS + hd] = d0;
                g_als[(m + 8) * NHEADS + hd] = s1;
                g_ald[(m + 8) * NHEADS + hd] = d1;
            }
        }
    }

    if (EPI == 2) {
        // fused SE column sums
        float cs[4][2];
#pragma unroll
        for (int ni = 0; ni < 4; ni++) {
            cs[ni][0] = 0.0f; cs[ni][1] = 0.0f;
#pragma unroll
            for (int mi = 0; mi < 4; mi++) {
                cs[ni][0] += acc[mi][ni][0] + acc[mi][ni][2];
                cs[ni][1] += acc[mi][ni][1] + acc[mi][ni][3];
            }
        }
#pragma unroll
        for (int ni = 0; ni < 4; ni++)
#pragma unroll
            for (int v = 0; v < 2; v++) {
                float t = cs[ni][v];
                t += __shfl_xor_sync(~0u, t, 4);
                t += __shfl_xor_sync(~0u, t, 8);
                t += __shfl_xor_sync(~0u, t, 16);
                cs[ni][v] = t;
            }
        if (lane < 4) {
#pragma unroll
            for (int ni = 0; ni < 4; ni++)
#pragma unroll
                for (int v = 0; v < 2; v++)
                    atomicAdd(&g_csum[nb * 128 + wn + ni * 8 + lane * 2 + v], cs[ni][v]);
        }
    }
}

// ---------------- GAT stencil hop: dedup softmax + source-union gather ----------------
__global__ __launch_bounds__(256)
void gat_stencil_kernel(const float* __restrict__ h,
                        const float* __restrict__ bias,
                        const float* __restrict__ gamma,
                        const float* __restrict__ beta,
                        const float* __restrict__ mean,
                        const float* __restrict__ var)
{
    __shared__ float s_bias[C2], s_scale[C2], s_shift[C2];
    __shared__ float sw[32][NHEADS][12];
    const int tid = threadIdx.x;
    {
        float sc = gamma[tid] * rsqrtf(var[tid] + 1e-5f);
        s_bias[tid]  = bias[tid];
        s_scale[tid] = sc;
        s_shift[tid] = beta[tid] - mean[tid] * sc;
    }

    const int nb0 = blockIdx.x * 32;

    // ---- phase 1 ----
    {
        const int di[11] = {-1, -1, -1,  0, 0,  1, 1, 1,  2, 0, 0};
        const int dj[11] = {-1,  0,  1, -1, 1, -1, 0, 1,  0, 2, 0};
        const int nl = tid >> 3, head = tid & 7;
        const int n = nb0 + nl;
        const int i = n / WImg, j = n % WImg;
        const float ald_v = g_ald[n * NHEADS + head];
        float ev[11];
        float mx = -1e30f;
#pragma unroll
        for (int k = 0; k < 11; k++) {
            int si = i - di[k], sj = j - dj[k];
            if ((unsigned)si < HImg && (unsigned)sj < WImg) {
                float e = g_als[(si * WImg + sj) * NHEADS + head] + ald_v;
                e = (e > 0.0f) ? e : 0.2f * e;
                ev[k] = e;
                mx = fmaxf(mx, e);
            } else ev[k] = -1e30f;
        }
        float sum = 0.0f;
#pragma unroll
        for (int k = 0; k < 11; k++) {
            float a = (ev[k] > -1e29f) ? expf(ev[k] - mx) : 0.0f;
            ev[k] = a;
            sum += a;
        }
        const float inv = 1.0f / (sum + 1e-16f);
#pragma unroll
        for (int k = 0; k < 11; k++) sw[nl][head][k] = ev[k] * inv;
    }
    __syncthreads();

    // ---- phase 2: warp per 4 nodes, source-union streaming ----
    const int w = tid >> 5, lane = tid & 31;
    const int head = lane >> 2;
    const int cb = lane * 8;
    const int j0l = w * 4;
    const int n0w = nb0 + j0l;
    const int i = n0w / WImg, j0 = n0w % WImg;

    float acc[4][8];
#pragma unroll
    for (int t = 0; t < 4; t++)
#pragma unroll
        for (int q = 0; q < 8; q++) acc[t][q] = 0.0f;

    if (i + 1 < HImg) {
        const float* rb = h + (size_t)(i + 1) * WImg * C2 + cb;
#pragma unroll
        for (int uu = -1; uu <= 4; uu++) {
            const int scn = j0 + uu;
            if ((unsigned)scn < WImg) {
                const float4* hp = (const float4*)(rb + (size_t)scn * C2);
                float4 v0 = hp[0], v1 = hp[1];
#pragma unroll
                for (int dj = -1; dj <= 1; dj++) {
                    const int t = uu + dj;
                    if (t >= 0 && t < 4) {
                        const float wt = sw[j0l + t][head][dj + 1];
                        FMA8(acc[t], wt, v0, v1);
                    }
                }
            }
        }
    }
    {
        const float* rb = h + (size_t)i * WImg * C2 + cb;
        const int djs[4] = {-1, 0, 1, 2};
        const int tps[4] = {3, 10, 4, 9};
#pragma unroll
        for (int uu = -2; uu <= 4; uu++) {
            const int scn = j0 + uu;
            if ((unsigned)scn < WImg) {
                const float4* hp = (const float4*)(rb + (size_t)scn * C2);
                float4 v0 = hp[0], v1 = hp[1];
#pragma unroll
                for (int q = 0; q < 4; q++) {
                    const int t = uu + djs[q];
                    if (t >= 0 && t < 4) {
                        const float wt = sw[j0l + t][head][tps[q]];
                        FMA8(acc[t], wt, v0, v1);
                    }
                }
            }
        }
    }
    if (i - 1 >= 0) {
        const float* rb = h + (size_t)(i - 1) * WImg * C2 + cb;
#pragma unroll
        for (int uu = -1; uu <= 4; uu++) {
            const int scn = j0 + uu;
            if ((unsigned)scn < WImg) {
                const float4* hp = (const float4*)(rb + (size_t)scn * C2);
                float4 v0 = hp[0], v1 = hp[1];
#pragma unroll
                for (int dj = -1; dj <= 1; dj++) {
                    const int t = uu + dj;
                    if (t >= 0 && t < 4) {
                        const float wt = sw[j0l + t][head][dj + 6];
                        FMA8(acc[t], wt, v0, v1);
                    }
                }
            }
        }
    }
    if (i - 2 >= 0) {
        const float* rb = h + (size_t)(i - 2) * WImg * C2 + cb;
#pragma unroll
        for (int uu = 0; uu <= 3; uu++) {
            const int scn = j0 + uu;
            const float4* hp = (const float4*)(rb + (size_t)scn * C2);
            float4 v0 = hp[0], v1 = hp[1];
            const float wt = sw[j0l + uu][head][8];
            FMA8(acc[uu], wt, v0, v1);
        }
    }

#pragma unroll
    for (int t = 0; t < 4; t++) {
        const int n = n0w + t;
        float4* xp = (float4*)&g_xf[(size_t)n * C2 + cb];
        float4 x0 = xp[0], x1 = xp[1];
        float o[8] = {x0.x, x0.y, x0.z, x0.w, x1.x, x1.y, x1.z, x1.w};
#pragma unroll
        for (int q = 0; q < 8; q++) {
            int c = cb + q;
            float g = acc[t][q] + s_bias[c];
            g = fmaf(g, s_scale[c], s_shift[c]);
            g = fmaxf(g, 0.0f);
            o[q] += g;
        }
        xp[0] = make_float4(o[0], o[1], o[2], o[3]);
        xp[1] = make_float4(o[4], o[5], o[6], o[7]);

        __nv_bfloat162 ph[4], pl[4];
#pragma unroll
        for (int q = 0; q < 4; q++) split2(o[2 * q], o[2 * q + 1], &ph[q], &pl[q]);
        *(uint4*)&g_ah[(size_t)n * C2 + cb] = *(uint4*)ph;
        *(uint4*)&g_al[(size_t)n * C2 + cb] = *(uint4*)pl;
    }
}

// ---------------- SE block ----------------
__device__ float g_sescale[C2];

__global__ void se_kernel(const float* __restrict__ w1, const float* __restrict__ b1,
                          const float* __restrict__ w2, const float* __restrict__ b2)
{
    __shared__ float mean_s[C2];
    __shared__ float t1[64];
    const int tx = threadIdx.x;
    mean_s[tx] = g_csum[tx] * (1.0f / (float)NN);
    __syncthreads();
    if (tx < 64) {
        float a = b1[tx];
        for (int c = 0; c < C2; c++) a = fmaf(mean_s[c], w1[tx * C2 + c], a);
        t1[tx] = fmaxf(a, 0.0f);
    }
    __syncthreads();
    float a = b2[tx];
#pragma unroll
    for (int jq = 0; jq < 64; jq++) a = fmaf(t1[jq], w2[tx * 64 + jq], a);
    g_sescale[tx] = 1.0f / (1.0f + expf(-a));
}

// ---------------- final fuse: out = y * se + identity (CHW) ----------------
__global__ void final_kernel(float* __restrict__ out) {
    int idx = blockIdx.x * blockDim.x + threadIdx.x;
    int e = idx * 4;
    int c = e / NN;
    float s = g_sescale[c];
    float4 y  = *(const float4*)&g_y[e];
    float4 id = *(const float4*)&g_id[e];
    float4 o;
    o.x = fmaf(y.x, s, id.x); o.y = fmaf(y.y, s, id.y);
    o.z = fmaf(y.z, s, id.z); o.w = fmaf(y.w, s, id.w);
    *(float4*)&out[e] = o;
}

// ---------------- launch ----------------
extern "C" void kernel_launch(void* const* d_in, const int* in_sizes, int n_in,
                              void* d_out, int out_size)
{
    const float* x        = (const float*)d_in[0];
    const float* w_id     = (const float*)d_in[1];
    const float* w_in     = (const float*)d_in[2];
    const float* w_gat    = (const float*)d_in[3];
    const float* a_src    = (const float*)d_in[4];
    const float* a_dst    = (const float*)d_in[5];
    const float* gat_bias = (const float*)d_in[6];
    const float* bn_gamma = (const float*)d_in[7];
    const float* bn_beta  = (const float*)d_in[8];
    const float* bn_mean  = (const float*)d_in[9];
    const float* bn_var   = (const float*)d_in[10];
    const float* w_out    = (const float*)d_in[11];
    const float* se_w1    = (const float*)d_in[12];
    const float* se_b1    = (const float*)d_in[13];
    const float* se_w2    = (const float*)d_in[14];
    const float* se_b2    = (const float*)d_in[15];
    float* out = (float*)d_out;

    float* hb;
    __nv_bfloat16 *wh, *wl;
    cudaGetSymbolAddress((void**)&hb, g_h);
    cudaGetSymbolAddress((void**)&wh, g_wh);
    cudaGetSymbolAddress((void**)&wl, g_wl);

    constexpr int SMEM_GEMM = 8 * STG;   // 81920 bytes
    cudaFuncSetAttribute(gemm_mma<C1, 0>, cudaFuncAttributeMaxDynamicSharedMemorySize, SMEM_GEMM);
    cudaFuncSetAttribute(gemm_mma<C2, 1>, cudaFuncAttributeMaxDynamicSharedMemorySize, SMEM_GEMM);
    cudaFuncSetAttribute(gemm_mma<C2, 2>, cudaFuncAttributeMaxDynamicSharedMemorySize, SMEM_GEMM);

    // 1) transpose+split x; split weights (+ zero csum)
    transpose_kernel<<<dim3(NN / 32, C1 / 32), dim3(32, 8)>>>(x);
    wsplit_kernel<<<W_TOTAL / 256, 256>>>(w_in, w_id, w_gat, w_out);

    // 2) fused: xf = xT @ w_in^T (row-major + split) + id = xT @ w_id^T (CHW)
    gemm_mma<C1, 0><<<dim3(NN / 128, 4), 256, SMEM_GEMM>>>(wh + WIN_OFF, wl + WIN_OFF,
                                                           nullptr, nullptr);

    // 3) GAT hops (logits fused into GEMM epilogue)
    for (int l = 0; l < 2; l++) {
        gemm_mma<C2, 1><<<dim3(NN / 128, 2), 256, SMEM_GEMM>>>(
            wh + WGAT_OFF + (size_t)l * C2 * C2, wl + WGAT_OFF + (size_t)l * C2 * C2,
            a_src + l * NHEADS * DHEAD, a_dst + l * NHEADS * DHEAD);
        gat_stencil_kernel<<<NN / 32, 256>>>(
            hb, gat_bias + l * C2, bn_gamma + l * C2, bn_beta + l * C2,
            bn_mean + l * C2, bn_var + l * C2);
    }

    // 4) y = xf @ w_out^T (CHW) + fused SE column sums
    gemm_mma<C2, 2><<<dim3(NN / 128, 2), 256, SMEM_GEMM>>>(wh + WOUT_OFF, wl + WOUT_OFF,
                                                           nullptr, nullptr);

    // 5) SE + final fuse
    se_kernel<<<1, C2>>>(se_w1, se_b1, se_w2, se_b2);
    final_kernel<<<(NN * C2 / 4) / 256, 256>>>(out);
}